// round 2
// baseline (speedup 1.0000x reference)
#include <cuda_runtime.h>
#include <cuda_bf16.h>

// Spiking MLP: s2 = ((x @ W1^T >= 1) @ W2^T >= 1)
//   x  [4096, 3136]  (binary 0/1 floats)
//   W1 [6272, 3136]
//   W2 [500, 6272]
//   out[4096, 500]
//
// Round 1: fp32 SIMT tiled GEMM with fused threshold epilogue.
// s1 staged in a __device__ global scratch buffer (allocation-free rule).

#define BM 128
#define BN 128
#define BK 8
#define TM 8
#define TN 8
#define NTHREADS 256

static const int M_BATCH = 4096;
static const int FEAT    = 6272;
static const int IN_DIM  = 3136;
static const int OUT_DIM = 500;

// hidden spikes scratch: 4096 * 6272 floats = 102.8 MB
__device__ float g_s1[4096ull * 6272ull];

// C = threshold(A @ B^T), A [M,K] row-major, B [N,K] row-major (torch weight layout).
// M assumed multiple of BM, K multiple of BK and of 4; N may be ragged.
__global__ __launch_bounds__(NTHREADS, 2)
void spike_gemm_kernel(const float* __restrict__ A,
                       const float* __restrict__ B,
                       float* __restrict__ C,
                       int M, int N, int K)
{
    __shared__ float As[BK][BM];
    __shared__ float Bs[BK][BN];

    const int tid = threadIdx.x;
    const int tx  = tid % 16;          // column group
    const int ty  = tid / 16;          // row group
    const int m0  = blockIdx.y * BM;
    const int n0  = blockIdx.x * BN;

    // global-load mapping: 256 threads load 128 rows x 8 k's, float4 each
    const int lr = tid >> 1;           // tile row 0..127
    const int lc = (tid & 1) * 4;      // k offset 0 or 4

    float acc[TM][TN];
#pragma unroll
    for (int i = 0; i < TM; i++)
#pragma unroll
        for (int j = 0; j < TN; j++) acc[i][j] = 0.f;

    const float* Aptr = A + (size_t)(m0 + lr) * K + lc;
    const bool   brow_ok = (n0 + lr) < N;
    const float* Bptr = B + (size_t)(n0 + lr) * K + lc;

    for (int k0 = 0; k0 < K; k0 += BK) {
        float4 av = *(const float4*)(Aptr + k0);
        float4 bv = brow_ok ? *(const float4*)(Bptr + k0)
                            : make_float4(0.f, 0.f, 0.f, 0.f);
        As[lc + 0][lr] = av.x;
        As[lc + 1][lr] = av.y;
        As[lc + 2][lr] = av.z;
        As[lc + 3][lr] = av.w;
        Bs[lc + 0][lr] = bv.x;
        Bs[lc + 1][lr] = bv.y;
        Bs[lc + 2][lr] = bv.z;
        Bs[lc + 3][lr] = bv.w;
        __syncthreads();

#pragma unroll
        for (int kk = 0; kk < BK; kk++) {
            float a[TM], b[TN];
            float4 a0 = *(const float4*)&As[kk][ty * TM];
            float4 a1 = *(const float4*)&As[kk][ty * TM + 4];
            float4 b0 = *(const float4*)&Bs[kk][tx * TN];
            float4 b1 = *(const float4*)&Bs[kk][tx * TN + 4];
            a[0] = a0.x; a[1] = a0.y; a[2] = a0.z; a[3] = a0.w;
            a[4] = a1.x; a[5] = a1.y; a[6] = a1.z; a[7] = a1.w;
            b[0] = b0.x; b[1] = b0.y; b[2] = b0.z; b[3] = b0.w;
            b[4] = b1.x; b[5] = b1.y; b[6] = b1.z; b[7] = b1.w;
#pragma unroll
            for (int i = 0; i < TM; i++)
#pragma unroll
                for (int j = 0; j < TN; j++)
                    acc[i][j] = fmaf(a[i], b[j], acc[i][j]);
        }
        __syncthreads();
    }

    // fused threshold epilogue (hard-reset IF neuron, single step, v0 = 0)
#pragma unroll
    for (int i = 0; i < TM; i++) {
        const int row = m0 + ty * TM + i;
#pragma unroll
        for (int j = 0; j < TN; j++) {
            const int col = n0 + tx * TN + j;
            if (col < N)
                C[(size_t)row * N + col] = (acc[i][j] >= 1.0f) ? 1.0f : 0.0f;
        }
    }
}

extern "C" void kernel_launch(void* const* d_in, const int* in_sizes, int n_in,
                              void* d_out, int out_size)
{
    const float* x  = (const float*)d_in[0];   // [4096, 3136]
    const float* W1 = (const float*)d_in[1];   // [6272, 3136]
    const float* W2 = (const float*)d_in[2];   // [500, 6272]
    float* out = (float*)d_out;                // [4096, 500]

    float* s1 = nullptr;
    cudaGetSymbolAddress((void**)&s1, g_s1);

    // GEMM1: s1 = threshold(x @ W1^T)   M=4096, N=6272, K=3136
    {
        dim3 grid(FEAT / BN, M_BATCH / BM);   // (49, 32)
        spike_gemm_kernel<<<grid, NTHREADS>>>(x, W1, s1, M_BATCH, FEAT, IN_DIM);
    }
    // GEMM2: out = threshold(s1 @ W2^T)  M=4096, N=500, K=6272
    {
        dim3 grid((OUT_DIM + BN - 1) / BN, M_BATCH / BM);  // (4, 32)
        spike_gemm_kernel<<<grid, NTHREADS>>>(s1, W2, out, M_BATCH, OUT_DIM, FEAT);
    }
}